// round 11
// baseline (speedup 1.0000x reference)
#include <cuda_runtime.h>
#include <cuda_bf16.h>
#include <stdint.h>

// Problem constants (fixed by the dataset)
#define N_NODES_MAX 50000
#define N_EDGES_MAX 800000
#define IN_F   128
#define HID    256
#define HID2   128
#define N_CLS  2

// ---------------- scratch (static device globals; no allocation) -------------
__device__ int   g_i64;                              // 1 if edge_index is int64
__device__ int   g_deg[N_NODES_MAX];
__device__ int   g_off[N_NODES_MAX + 1];
__device__ int   g_cursor[N_NODES_MAX];
__device__ int   g_part[256];                        // per-block degree sums
__device__ int   g_partoff[256];                     // exclusive prefix of block sums
__device__ __align__(16) float g_deginv[N_NODES_MAX];
__device__ __align__(16) int   g_src[N_EDGES_MAX];   // CSR: src node per in-edge (grouped by dst)
__device__ __align__(16) float g_agg[(size_t)N_NODES_MAX * HID];   // agg buffer (max width 256)
__device__ __align__(16) float g_h1 [(size_t)N_NODES_MAX * HID];   // layer-1 activations [N,256]
__device__ __align__(16) float g_h2 [(size_t)N_NODES_MAX * HID2];  // layer-2 activations [N,128]

__device__ __forceinline__ void f4_acc(float4& a, const float4& v) {
    a.x += v.x; a.y += v.y; a.z += v.z; a.w += v.w;
}

// ---- packed fp32x2 helpers (FFMA2 path; exact fp32 semantics per half) ------
__device__ __forceinline__ unsigned long long pack2(float lo, float hi) {
    unsigned long long r;
    asm("mov.b64 %0, {%1, %2};" : "=l"(r) : "f"(lo), "f"(hi));
    return r;
}
__device__ __forceinline__ void unpack2(float& lo, float& hi, unsigned long long v) {
    asm("mov.b64 {%0, %1}, %2;" : "=f"(lo), "=f"(hi) : "l"(v));
}
__device__ __forceinline__ void fma2(unsigned long long& d,
                                     unsigned long long a, unsigned long long b) {
    asm("fma.rn.f32x2 %0, %1, %2, %3;" : "=l"(d) : "l"(a), "l"(b), "l"(d));
}

// Read edge value e from the row (idx=0) or col (idx=1) stream, honoring dtype.
__device__ __forceinline__ int edge_at(const void* edges, int E, int which, int e) {
    if (g_i64) {
        const long long* p = (const long long*)edges;
        return (int)p[(size_t)which * E + e];
    } else {
        const int* p = (const int*)edges;
        return p[(size_t)which * E + e];
    }
}

// ---------------- dtype detect -----------------------------------------------
__global__ void detect_dtype_kernel(const int* __restrict__ raw, int E) {
    __shared__ int nz;
    if (threadIdx.x == 0) nz = 0;
    __syncthreads();
    int samples = min(1024, E);
    for (int i = threadIdx.x; i < samples; i += blockDim.x) {
        if (raw[2 * i + 1] != 0) atomicOr(&nz, 1);
    }
    __syncthreads();
    if (threadIdx.x == 0) g_i64 = (nz == 0) ? 1 : 0;
}

// ---------------- CSR build --------------------------------------------------
__global__ void zero_deg_kernel(int n) {
    int i = blockIdx.x * blockDim.x + threadIdx.x;
    if (i < n) g_deg[i] = 0;
}

__global__ void hist_kernel(const void* __restrict__ edges, int E, int n) {
    int e = blockIdx.x * blockDim.x + threadIdx.x;
    if (e < E) {
        int d = edge_at(edges, E, 1, e);     // col
        d = max(0, min(d, n - 1));
        atomicAdd(&g_deg[d], 1);
    }
}

// --- parallel 3-pass scan: partials -> scan partials -> per-block rescan ------
__global__ void scan_partial_kernel(int n) {
    __shared__ int s[256];
    int b = blockIdx.x, t = threadIdx.x;
    int i = b * 256 + t;
    s[t] = (i < n) ? g_deg[i] : 0;
    __syncthreads();
    #pragma unroll
    for (int off = 128; off > 0; off >>= 1) {
        if (t < off) s[t] += s[t + off];
        __syncthreads();
    }
    if (t == 0) g_part[b] = s[0];
}

__global__ void scan_blocksums_kernel(int nb) {
    __shared__ int s[256];
    int t = threadIdx.x;
    int v = (t < nb) ? g_part[t] : 0;
    s[t] = v;
    __syncthreads();
    #pragma unroll
    for (int off = 1; off < 256; off <<= 1) {
        int u = (t >= off) ? s[t - off] : 0;
        __syncthreads();
        s[t] += u;
        __syncthreads();
    }
    if (t < nb) g_partoff[t] = s[t] - v;     // exclusive
}

__global__ void scan_final_kernel(int n) {
    __shared__ int s[256];
    int b = blockIdx.x, t = threadIdx.x;
    int i = b * 256 + t;
    int d = (i < n) ? g_deg[i] : 0;
    s[t] = d;
    __syncthreads();
    #pragma unroll
    for (int off = 1; off < 256; off <<= 1) {   // inclusive scan
        int u = (t >= off) ? s[t - off] : 0;
        __syncthreads();
        s[t] += u;
        __syncthreads();
    }
    int base = g_partoff[b];
    if (i < n) {
        int excl = base + s[t] - d;
        g_off[i]    = excl;
        g_cursor[i] = excl;
        g_deginv[i] = 1.0f / fmaxf((float)d, 1.0f);
        if (i == n - 1) g_off[n] = excl + d;
    }
}

__global__ void scatter_kernel(const void* __restrict__ edges, int E, int n) {
    int e = blockIdx.x * blockDim.x + threadIdx.x;
    if (e < E) {
        int d = edge_at(edges, E, 1, e);     // col (dst)
        d = max(0, min(d, n - 1));
        int s = edge_at(edges, E, 0, e);     // row (src)
        s = max(0, min(s, n - 1));
        int p = atomicAdd(&g_cursor[d], 1);
        if (p >= 0 && p < N_EDGES_MAX) g_src[p] = s;
    }
}

// ---------------- aggregation: warp per node, float4 gathers, 4-way unroll ----
template <int F, bool FROM_X>
__global__ void agg_kernel(const float* __restrict__ xin, int M) {
    const float* __restrict__ feat = FROM_X ? xin : (const float*)g_h1;
    int gw   = (blockIdx.x * blockDim.x + threadIdx.x) >> 5;
    int lane = threadIdx.x & 31;
    if (gw >= M) return;
    int beg = g_off[gw];
    int end = g_off[gw + 1];

    float4 acc0 = make_float4(0.f, 0.f, 0.f, 0.f);
    float4 acc1 = make_float4(0.f, 0.f, 0.f, 0.f);

    int i = beg;
    for (; i + 3 < end; i += 4) {
        int s0 = g_src[i], s1 = g_src[i + 1], s2 = g_src[i + 2], s3 = g_src[i + 3];
        const float4* r0 = (const float4*)(feat + (size_t)s0 * F);
        const float4* r1 = (const float4*)(feat + (size_t)s1 * F);
        const float4* r2 = (const float4*)(feat + (size_t)s2 * F);
        const float4* r3 = (const float4*)(feat + (size_t)s3 * F);
        float4 v0 = r0[lane], v1 = r1[lane], v2 = r2[lane], v3 = r3[lane];
        if (F == 256) {
            float4 w0 = r0[lane + 32], w1 = r1[lane + 32];
            float4 w2 = r2[lane + 32], w3 = r3[lane + 32];
            f4_acc(acc1, w0); f4_acc(acc1, w1); f4_acc(acc1, w2); f4_acc(acc1, w3);
        }
        f4_acc(acc0, v0); f4_acc(acc0, v1); f4_acc(acc0, v2); f4_acc(acc0, v3);
    }
    for (; i < end; ++i) {
        int s0 = g_src[i];
        const float4* r0 = (const float4*)(feat + (size_t)s0 * F);
        f4_acc(acc0, r0[lane]);
        if (F == 256) f4_acc(acc1, r0[lane + 32]);
    }

    float dinv = g_deginv[gw];
    float4* o = (float4*)((float*)g_agg + (size_t)gw * F);
    acc0.x *= dinv; acc0.y *= dinv; acc0.z *= dinv; acc0.w *= dinv;
    o[lane] = acc0;
    if (F == 256) {
        acc1.x *= dinv; acc1.y *= dinv; acc1.z *= dinv; acc1.w *= dinv;
        o[lane + 32] = acc1;
    }
}

// ---------------- tiled SGEMM via packed fma.rn.f32x2 -------------------------
// C[M,N] = g_agg[M,K] @ W[N,K]^T + bias, ReLU.
// Tile 128x64 (MxN), BK=16, 256 threads, 8x4 micro-tile held as
// 4 M-pairs x 4 N-cols of packed f32x2 accumulators (FFMA2: 2 FMA/instr).
// Smem pitch +4 keeps float4 LDS 16B-aligned.
// OUT=1 -> writes g_h1 ; OUT=2 -> writes g_h2.
template <int K, int OUT>
__global__ void gemm_bias_kernel(const float* __restrict__ W,
                                 const float* __restrict__ bias,
                                 int M, int N) {
    const float* __restrict__ A = (const float*)g_agg;
    float* __restrict__ C = (OUT == 1) ? (float*)g_h1 : (float*)g_h2;

    __shared__ __align__(16) float As[16][132];
    __shared__ __align__(16) float Bs[16][68];

    int tid = threadIdx.x;            // 0..255
    int tx  = tid & 15;               // N micro: 4 cols each
    int ty  = tid >> 4;               // M micro: 8 rows each (4 packed pairs)
    int m0  = blockIdx.y * 128;
    int n0  = blockIdx.x * 64;

    unsigned long long accp[4][4];    // [m-pair][n-col], each packs rows (2i, 2i+1)
    #pragma unroll
    for (int i = 0; i < 4; ++i)
        #pragma unroll
        for (int j = 0; j < 4; ++j) accp[i][j] = 0ull;

    int lr = tid >> 4;   // 0..15
    int lc = tid & 15;   // k within 16

    for (int k0 = 0; k0 < K; k0 += 16) {
        #pragma unroll
        for (int i = 0; i < 8; ++i) {
            int m = m0 + lr + i * 16;
            As[lc][lr + i * 16] = (m < M) ? A[(size_t)m * K + k0 + lc] : 0.f;
        }
        #pragma unroll
        for (int i = 0; i < 4; ++i) {
            int n = n0 + lr + i * 16;        // N is a multiple of 64
            Bs[lc][lr + i * 16] = W[(size_t)n * K + k0 + lc];
        }
        __syncthreads();

        #pragma unroll
        for (int kk = 0; kk < 16; ++kk) {
            float4 b4 = *(const float4*)&Bs[kk][tx * 4];
            float4 a0 = *(const float4*)&As[kk][ty * 8];
            float4 a1 = *(const float4*)&As[kk][ty * 8 + 4];
            // A pairs along M: consecutive registers -> near-free packs
            unsigned long long ap[4];
            ap[0] = pack2(a0.x, a0.y);
            ap[1] = pack2(a0.z, a0.w);
            ap[2] = pack2(a1.x, a1.y);
            ap[3] = pack2(a1.z, a1.w);
            // B broadcast packs (ALU movs, overlap with fma pipe)
            unsigned long long bb0 = pack2(b4.x, b4.x);
            unsigned long long bb1 = pack2(b4.y, b4.y);
            unsigned long long bb2 = pack2(b4.z, b4.z);
            unsigned long long bb3 = pack2(b4.w, b4.w);
            #pragma unroll
            for (int i = 0; i < 4; ++i) {
                fma2(accp[i][0], ap[i], bb0);
                fma2(accp[i][1], ap[i], bb1);
                fma2(accp[i][2], ap[i], bb2);
                fma2(accp[i][3], ap[i], bb3);
            }
        }
        __syncthreads();
    }

    float4 bv = *(const float4*)&bias[n0 + tx * 4];
    float bvv[4] = {bv.x, bv.y, bv.z, bv.w};
    #pragma unroll
    for (int i = 0; i < 4; ++i) {
        int mA = m0 + ty * 8 + 2 * i;        // even row of the pair
        int mB = mA + 1;                     // odd row
        float rowA[4], rowB[4];
        #pragma unroll
        for (int j = 0; j < 4; ++j) {
            unpack2(rowA[j], rowB[j], accp[i][j]);
            rowA[j] = fmaxf(rowA[j] + bvv[j], 0.f);
            rowB[j] = fmaxf(rowB[j] + bvv[j], 0.f);
        }
        if (mA < M)
            *(float4*)&C[(size_t)mA * N + n0 + tx * 4] =
                make_float4(rowA[0], rowA[1], rowA[2], rowA[3]);
        if (mB < M)
            *(float4*)&C[(size_t)mB * N + n0 + tx * 4] =
                make_float4(rowB[0], rowB[1], rowB[2], rowB[3]);
    }
}

// ---------------- final head: out[N,2] = g_h2 @ W3^T + b3 ---------------------
__global__ void head_kernel(const float* __restrict__ W3,
                            const float* __restrict__ b3,
                            float* __restrict__ out, int M) {
    __shared__ float w[2][HID2];
    __shared__ float b[2];
    for (int i = threadIdx.x; i < 2 * HID2; i += blockDim.x)
        w[i / HID2][i % HID2] = W3[i];
    if (threadIdx.x < 2) b[threadIdx.x] = b3[threadIdx.x];
    __syncthreads();

    int n = blockIdx.x * blockDim.x + threadIdx.x;
    if (n >= M) return;
    const float4* r = (const float4*)((const float*)g_h2 + (size_t)n * HID2);
    float s0 = b[0], s1 = b[1];
    #pragma unroll
    for (int i = 0; i < HID2 / 4; ++i) {
        float4 v = r[i];
        s0 += v.x * w[0][4 * i] + v.y * w[0][4 * i + 1] + v.z * w[0][4 * i + 2] + v.w * w[0][4 * i + 3];
        s1 += v.x * w[1][4 * i] + v.y * w[1][4 * i + 1] + v.z * w[1][4 * i + 2] + v.w * w[1][4 * i + 3];
    }
    out[(size_t)n * 2 + 0] = s0;
    out[(size_t)n * 2 + 1] = s1;
}

// ---------------- launch -----------------------------------------------------
extern "C" void kernel_launch(void* const* d_in, const int* in_sizes, int n_in,
                              void* d_out, int out_size) {
    const float* x     = (const float*)d_in[0];
    const void*  edges = d_in[1];            // [2, E], int32 OR int64 (detected on device)

    int wbase = 2;
    if (n_in >= 9 && in_sizes[2] <= 1) wbase = 3;
    const float* W1 = (const float*)d_in[wbase + 0];
    const float* b1 = (const float*)d_in[wbase + 1];
    const float* W2 = (const float*)d_in[wbase + 2];
    const float* b2 = (const float*)d_in[wbase + 3];
    const float* W3 = (const float*)d_in[wbase + 4];
    const float* b3 = (const float*)d_in[wbase + 5];
    float* out = (float*)d_out;

    int N = in_sizes[0] / IN_F;          // 50000
    int E = in_sizes[1] / 2;             // 800000
    if (N > N_NODES_MAX) N = N_NODES_MAX;
    if (E > N_EDGES_MAX) E = N_EDGES_MAX;

    int scanBlocks = (N + 255) / 256;    // 196 <= 256

    // dtype detect + CSR build
    detect_dtype_kernel<<<1, 256>>>((const int*)edges, E);
    zero_deg_kernel<<<(N + 255) / 256, 256>>>(N);
    hist_kernel<<<(E + 255) / 256, 256>>>(edges, E, N);
    scan_partial_kernel<<<scanBlocks, 256>>>(N);
    scan_blocksums_kernel<<<1, 256>>>(scanBlocks);
    scan_final_kernel<<<scanBlocks, 256>>>(N);
    scatter_kernel<<<(E + 255) / 256, 256>>>(edges, E, N);

    const int warpsPerBlock = 8;
    int aggBlocks = (N + warpsPerBlock - 1) / warpsPerBlock;

    // layer 1: agg(x) -> g_agg ; gemm(g_agg, W1) -> g_h1 (ReLU)
    agg_kernel<IN_F, true><<<aggBlocks, warpsPerBlock * 32>>>(x, N);
    {
        dim3 grid(HID / 64, (N + 127) / 128);
        gemm_bias_kernel<IN_F, 1><<<grid, 256>>>(W1, b1, N, HID);
    }
    // layer 2: agg(g_h1) -> g_agg ; gemm(g_agg, W2) -> g_h2 (ReLU)
    agg_kernel<HID, false><<<aggBlocks, warpsPerBlock * 32>>>(x, N);
    {
        dim3 grid(HID2 / 64, (N + 127) / 128);
        gemm_bias_kernel<HID, 2><<<grid, 256>>>(W2, b2, N, HID2);
    }
    // head
    head_kernel<<<(N + 127) / 128, 128>>>(W3, b3, out, N);
}

// round 12
// speedup vs baseline: 1.2946x; 1.2946x over previous
#include <cuda_runtime.h>
#include <cuda_bf16.h>
#include <stdint.h>

// Problem constants (fixed by the dataset)
#define N_NODES_MAX 50000
#define N_EDGES_MAX 800000
#define IN_F   128
#define HID    256
#define HID2   128
#define N_CLS  2

// ---------------- scratch (static device globals; no allocation) -------------
__device__ int   g_i64;
__device__ int   g_deg[N_NODES_MAX];
__device__ int   g_off[N_NODES_MAX + 1];
__device__ int   g_cursor[N_NODES_MAX];
__device__ int   g_part[256];
__device__ int   g_partoff[256];
__device__ __align__(16) float g_deginv[N_NODES_MAX];
__device__ __align__(16) int   g_src[N_EDGES_MAX];
// split-precision bf16 planes of the aggregated features (max width 256)
__device__ __align__(16) __nv_bfloat16 g_aggh[(size_t)N_NODES_MAX * HID];
__device__ __align__(16) __nv_bfloat16 g_aggl[(size_t)N_NODES_MAX * HID];
// split-precision weights
__device__ __align__(16) __nv_bfloat16 g_w1h[HID * IN_F],  g_w1l[HID * IN_F];
__device__ __align__(16) __nv_bfloat16 g_w2h[HID2 * HID],  g_w2l[HID2 * HID];
// activations
__device__ __align__(16) float g_h1[(size_t)N_NODES_MAX * HID];
__device__ __align__(16) float g_h2[(size_t)N_NODES_MAX * HID2];

__device__ __forceinline__ void f4_acc(float4& a, const float4& v) {
    a.x += v.x; a.y += v.y; a.z += v.z; a.w += v.w;
}

__device__ __forceinline__ uint32_t pack_bf2(float a, float b) {
    __nv_bfloat162 v = __floats2bfloat162_rn(a, b);
    return *(uint32_t*)&v;
}

// Read edge value e from row (0) or col (1) stream, honoring dtype.
__device__ __forceinline__ int edge_at(const void* edges, int E, int which, int e) {
    if (g_i64) {
        const long long* p = (const long long*)edges;
        return (int)p[(size_t)which * E + e];
    } else {
        const int* p = (const int*)edges;
        return p[(size_t)which * E + e];
    }
}

// ---------------- dtype detect -----------------------------------------------
__global__ void detect_dtype_kernel(const int* __restrict__ raw, int E) {
    __shared__ int nz;
    if (threadIdx.x == 0) nz = 0;
    __syncthreads();
    int samples = min(1024, E);
    for (int i = threadIdx.x; i < samples; i += blockDim.x) {
        if (raw[2 * i + 1] != 0) atomicOr(&nz, 1);
    }
    __syncthreads();
    if (threadIdx.x == 0) g_i64 = (nz == 0) ? 1 : 0;
}

// ---------------- CSR build --------------------------------------------------
__global__ void zero_deg_kernel(int n) {
    int i = blockIdx.x * blockDim.x + threadIdx.x;
    if (i < n) g_deg[i] = 0;
}

__global__ void hist_kernel(const void* __restrict__ edges, int E, int n) {
    int e = blockIdx.x * blockDim.x + threadIdx.x;
    if (e < E) {
        int d = edge_at(edges, E, 1, e);
        d = max(0, min(d, n - 1));
        atomicAdd(&g_deg[d], 1);
    }
}

__global__ void scan_partial_kernel(int n) {
    __shared__ int s[256];
    int b = blockIdx.x, t = threadIdx.x;
    int i = b * 256 + t;
    s[t] = (i < n) ? g_deg[i] : 0;
    __syncthreads();
    #pragma unroll
    for (int off = 128; off > 0; off >>= 1) {
        if (t < off) s[t] += s[t + off];
        __syncthreads();
    }
    if (t == 0) g_part[b] = s[0];
}

__global__ void scan_blocksums_kernel(int nb) {
    __shared__ int s[256];
    int t = threadIdx.x;
    int v = (t < nb) ? g_part[t] : 0;
    s[t] = v;
    __syncthreads();
    #pragma unroll
    for (int off = 1; off < 256; off <<= 1) {
        int u = (t >= off) ? s[t - off] : 0;
        __syncthreads();
        s[t] += u;
        __syncthreads();
    }
    if (t < nb) g_partoff[t] = s[t] - v;
}

__global__ void scan_final_kernel(int n) {
    __shared__ int s[256];
    int b = blockIdx.x, t = threadIdx.x;
    int i = b * 256 + t;
    int d = (i < n) ? g_deg[i] : 0;
    s[t] = d;
    __syncthreads();
    #pragma unroll
    for (int off = 1; off < 256; off <<= 1) {
        int u = (t >= off) ? s[t - off] : 0;
        __syncthreads();
        s[t] += u;
        __syncthreads();
    }
    int base = g_partoff[b];
    if (i < n) {
        int excl = base + s[t] - d;
        g_off[i]    = excl;
        g_cursor[i] = excl;
        g_deginv[i] = 1.0f / fmaxf((float)d, 1.0f);
        if (i == n - 1) g_off[n] = excl + d;
    }
}

__global__ void scatter_kernel(const void* __restrict__ edges, int E, int n) {
    int e = blockIdx.x * blockDim.x + threadIdx.x;
    if (e < E) {
        int d = edge_at(edges, E, 1, e);
        d = max(0, min(d, n - 1));
        int s = edge_at(edges, E, 0, e);
        s = max(0, min(s, n - 1));
        int p = atomicAdd(&g_cursor[d], 1);
        if (p >= 0 && p < N_EDGES_MAX) g_src[p] = s;
    }
}

// ---------------- weight split conversion ------------------------------------
// WHICH=1 -> g_w1h/g_w1l ; WHICH=2 -> g_w2h/g_w2l
template <int WHICH>
__global__ void conv_w_kernel(const float* __restrict__ W, int n) {
    int i = blockIdx.x * blockDim.x + threadIdx.x;
    if (i >= n) return;
    float w = W[i];
    __nv_bfloat16 h = __float2bfloat16(w);
    __nv_bfloat16 l = __float2bfloat16(w - __bfloat162float(h));
    if (WHICH == 1) { g_w1h[i] = h; g_w1l[i] = l; }
    else            { g_w2h[i] = h; g_w2l[i] = l; }
}

// ---------------- aggregation: warp/node, float4 gathers, bf16-split output ---
template <int F, bool FROM_X>
__global__ void agg_kernel(const float* __restrict__ xin, int M) {
    const float* __restrict__ feat = FROM_X ? xin : (const float*)g_h1;
    int gw   = (blockIdx.x * blockDim.x + threadIdx.x) >> 5;
    int lane = threadIdx.x & 31;
    if (gw >= M) return;
    int beg = g_off[gw];
    int end = g_off[gw + 1];

    float4 acc0 = make_float4(0.f, 0.f, 0.f, 0.f);
    float4 acc1 = make_float4(0.f, 0.f, 0.f, 0.f);

    int i = beg;
    for (; i + 3 < end; i += 4) {
        int s0 = g_src[i], s1 = g_src[i + 1], s2 = g_src[i + 2], s3 = g_src[i + 3];
        const float4* r0 = (const float4*)(feat + (size_t)s0 * F);
        const float4* r1 = (const float4*)(feat + (size_t)s1 * F);
        const float4* r2 = (const float4*)(feat + (size_t)s2 * F);
        const float4* r3 = (const float4*)(feat + (size_t)s3 * F);
        float4 v0 = r0[lane], v1 = r1[lane], v2 = r2[lane], v3 = r3[lane];
        if (F == 256) {
            float4 w0 = r0[lane + 32], w1 = r1[lane + 32];
            float4 w2 = r2[lane + 32], w3 = r3[lane + 32];
            f4_acc(acc1, w0); f4_acc(acc1, w1); f4_acc(acc1, w2); f4_acc(acc1, w3);
        }
        f4_acc(acc0, v0); f4_acc(acc0, v1); f4_acc(acc0, v2); f4_acc(acc0, v3);
    }
    for (; i < end; ++i) {
        int s0 = g_src[i];
        const float4* r0 = (const float4*)(feat + (size_t)s0 * F);
        f4_acc(acc0, r0[lane]);
        if (F == 256) f4_acc(acc1, r0[lane + 32]);
    }

    float dinv = g_deginv[gw];
    // split fp32 -> bf16 hi + bf16 lo, write both planes
    {
        float vx = acc0.x * dinv, vy = acc0.y * dinv, vz = acc0.z * dinv, vw = acc0.w * dinv;
        float hx = __bfloat162float(__float2bfloat16(vx));
        float hy = __bfloat162float(__float2bfloat16(vy));
        float hz = __bfloat162float(__float2bfloat16(vz));
        float hw = __bfloat162float(__float2bfloat16(vw));
        size_t idx = (size_t)gw * F + lane * 4;
        *(uint2*)&g_aggh[idx] = make_uint2(pack_bf2(hx, hy), pack_bf2(hz, hw));
        *(uint2*)&g_aggl[idx] = make_uint2(pack_bf2(vx - hx, vy - hy), pack_bf2(vz - hz, vw - hw));
    }
    if (F == 256) {
        float vx = acc1.x * dinv, vy = acc1.y * dinv, vz = acc1.z * dinv, vw = acc1.w * dinv;
        float hx = __bfloat162float(__float2bfloat16(vx));
        float hy = __bfloat162float(__float2bfloat16(vy));
        float hz = __bfloat162float(__float2bfloat16(vz));
        float hw = __bfloat162float(__float2bfloat16(vw));
        size_t idx = (size_t)gw * F + 128 + lane * 4;
        *(uint2*)&g_aggh[idx] = make_uint2(pack_bf2(hx, hy), pack_bf2(hz, hw));
        *(uint2*)&g_aggl[idx] = make_uint2(pack_bf2(vx - hx, vy - hy), pack_bf2(vz - hz, vw - hw));
    }
}

// ---------------- bf16 split-precision tensor-core GEMM -----------------------
// C[M,N] = A[M,K] @ W[N,K]^T + bias, ReLU, where A = Ah+Al, W = Wh+Wl (bf16).
// C += Ah*Wh + Ah*Wl + Al*Wh (fp32 accum; lo*lo dropped, ~2^-18 rel).
// Block: 128x64 tile, 256 thr, 8 warps as 4(M)x2(N); warp tile 32x32 = 2x4 mmas
// of m16n8k16. Smem pitch 40 bf16 (20 b32): conflict-free fragment LDS.
#define SMP 40   // smem row pitch in bf16

__device__ __forceinline__ void mma_bf16(float* c, const uint32_t* a, const uint32_t* b) {
    asm volatile(
        "mma.sync.aligned.m16n8k16.row.col.f32.bf16.bf16.f32 "
        "{%0,%1,%2,%3}, {%4,%5,%6,%7}, {%8,%9}, {%0,%1,%2,%3};"
        : "+f"(c[0]), "+f"(c[1]), "+f"(c[2]), "+f"(c[3])
        : "r"(a[0]), "r"(a[1]), "r"(a[2]), "r"(a[3]), "r"(b[0]), "r"(b[1]));
}

__device__ __forceinline__ uint32_t lds_b32(const __nv_bfloat16* s, int row, int colb32) {
    return *(const uint32_t*)&s[row * SMP + colb32 * 2];
}

template <int K, int OUT>
__global__ void gemm_mma_kernel(const float* __restrict__ bias, int M, int N) {
    const __nv_bfloat16* __restrict__ Wh = (OUT == 1) ? g_w1h : g_w2h;
    const __nv_bfloat16* __restrict__ Wl = (OUT == 1) ? g_w1l : g_w2l;
    float* __restrict__ C = (OUT == 1) ? (float*)g_h1 : (float*)g_h2;

    __shared__ __align__(16) __nv_bfloat16 sAh[128 * SMP];
    __shared__ __align__(16) __nv_bfloat16 sAl[128 * SMP];
    __shared__ __align__(16) __nv_bfloat16 sBh[64 * SMP];
    __shared__ __align__(16) __nv_bfloat16 sBl[64 * SMP];

    int tid  = threadIdx.x;
    int wid  = tid >> 5;
    int lane = tid & 31;
    int g    = lane >> 2;       // groupID
    int t    = lane & 3;        // thread-in-group
    int warpM = wid >> 1;       // 0..3
    int warpN = wid & 1;        // 0..1
    int m0 = blockIdx.y * 128;
    int n0 = blockIdx.x * 64;

    float c[2][4][4];
    #pragma unroll
    for (int mi = 0; mi < 2; ++mi)
        #pragma unroll
        for (int ni = 0; ni < 4; ++ni)
            #pragma unroll
            for (int j = 0; j < 4; ++j) c[mi][ni][j] = 0.f;

    // load mappings
    int arow = tid >> 1, aseg = tid & 1;      // A: 128 rows x 2 segs of 16 bf16
    int brow = tid >> 2, bseg = tid & 3;      // B: 64 rows x 4 segs of 8 bf16

    for (int k0 = 0; k0 < K; k0 += 32) {
        // stage A (hi+lo)
        {
            int m = m0 + arow;
            uint4 z = make_uint4(0, 0, 0, 0);
            uint4 h0 = z, h1 = z, l0 = z, l1 = z;
            if (m < M) {
                size_t go = (size_t)m * K + k0 + aseg * 16;
                h0 = *(const uint4*)&g_aggh[go];
                h1 = *(const uint4*)&g_aggh[go + 8];
                l0 = *(const uint4*)&g_aggl[go];
                l1 = *(const uint4*)&g_aggl[go + 8];
            }
            int so = arow * SMP + aseg * 16;
            *(uint4*)&sAh[so] = h0; *(uint4*)&sAh[so + 8] = h1;
            *(uint4*)&sAl[so] = l0; *(uint4*)&sAl[so + 8] = l1;
        }
        // stage B (hi+lo); N % 64 == 0 so rows always valid
        {
            size_t go = (size_t)(n0 + brow) * K + k0 + bseg * 8;
            int so = brow * SMP + bseg * 8;
            *(uint4*)&sBh[so] = *(const uint4*)&Wh[go];
            *(uint4*)&sBl[so] = *(const uint4*)&Wl[go];
        }
        __syncthreads();

        #pragma unroll
        for (int ks = 0; ks < 32; ks += 16) {
            int koff = ks >> 1;   // b32 column offset
            uint32_t ah[2][4], al[2][4];
            #pragma unroll
            for (int mi = 0; mi < 2; ++mi) {
                int rb = warpM * 32 + mi * 16;
                ah[mi][0] = lds_b32(sAh, rb + g,     koff + t);
                ah[mi][1] = lds_b32(sAh, rb + g + 8, koff + t);
                ah[mi][2] = lds_b32(sAh, rb + g,     koff + t + 4);
                ah[mi][3] = lds_b32(sAh, rb + g + 8, koff + t + 4);
                al[mi][0] = lds_b32(sAl, rb + g,     koff + t);
                al[mi][1] = lds_b32(sAl, rb + g + 8, koff + t);
                al[mi][2] = lds_b32(sAl, rb + g,     koff + t + 4);
                al[mi][3] = lds_b32(sAl, rb + g + 8, koff + t + 4);
            }
            uint32_t bh[4][2], bl[4][2];
            #pragma unroll
            for (int ni = 0; ni < 4; ++ni) {
                int nb = warpN * 32 + ni * 8;
                bh[ni][0] = lds_b32(sBh, nb + g, koff + t);
                bh[ni][1] = lds_b32(sBh, nb + g, koff + t + 4);
                bl[ni][0] = lds_b32(sBl, nb + g, koff + t);
                bl[ni][1] = lds_b32(sBl, nb + g, koff + t + 4);
            }
            #pragma unroll
            for (int mi = 0; mi < 2; ++mi)
                #pragma unroll
                for (int ni = 0; ni < 4; ++ni) {
                    mma_bf16(c[mi][ni], ah[mi], bh[ni]);   // hi*hi
                    mma_bf16(c[mi][ni], ah[mi], bl[ni]);   // hi*lo
                    mma_bf16(c[mi][ni], al[mi], bh[ni]);   // lo*hi
                }
        }
        __syncthreads();
    }

    // epilogue: bias + ReLU, guarded stores
    #pragma unroll
    for (int mi = 0; mi < 2; ++mi) {
        int row0 = m0 + warpM * 32 + mi * 16 + g;
        int row1 = row0 + 8;
        #pragma unroll
        for (int ni = 0; ni < 4; ++ni) {
            int col = n0 + warpN * 32 + ni * 8 + 2 * t;
            float b0 = bias[col], b1 = bias[col + 1];
            if (row0 < M) {
                float2 v;
                v.x = fmaxf(c[mi][ni][0] + b0, 0.f);
                v.y = fmaxf(c[mi][ni][1] + b1, 0.f);
                *(float2*)&C[(size_t)row0 * N + col] = v;
            }
            if (row1 < M) {
                float2 v;
                v.x = fmaxf(c[mi][ni][2] + b0, 0.f);
                v.y = fmaxf(c[mi][ni][3] + b1, 0.f);
                *(float2*)&C[(size_t)row1 * N + col] = v;
            }
        }
    }
}

// ---------------- final head: out[N,2] = g_h2 @ W3^T + b3 ---------------------
__global__ void head_kernel(const float* __restrict__ W3,
                            const float* __restrict__ b3,
                            float* __restrict__ out, int M) {
    __shared__ float w[2][HID2];
    __shared__ float b[2];
    for (int i = threadIdx.x; i < 2 * HID2; i += blockDim.x)
        w[i / HID2][i % HID2] = W3[i];
    if (threadIdx.x < 2) b[threadIdx.x] = b3[threadIdx.x];
    __syncthreads();

    int n = blockIdx.x * blockDim.x + threadIdx.x;
    if (n >= M) return;
    const float4* r = (const float4*)((const float*)g_h2 + (size_t)n * HID2);
    float s0 = b[0], s1 = b[1];
    #pragma unroll
    for (int i = 0; i < HID2 / 4; ++i) {
        float4 v = r[i];
        s0 += v.x * w[0][4 * i] + v.y * w[0][4 * i + 1] + v.z * w[0][4 * i + 2] + v.w * w[0][4 * i + 3];
        s1 += v.x * w[1][4 * i] + v.y * w[1][4 * i + 1] + v.z * w[1][4 * i + 2] + v.w * w[1][4 * i + 3];
    }
    out[(size_t)n * 2 + 0] = s0;
    out[(size_t)n * 2 + 1] = s1;
}

// ---------------- launch -----------------------------------------------------
extern "C" void kernel_launch(void* const* d_in, const int* in_sizes, int n_in,
                              void* d_out, int out_size) {
    const float* x     = (const float*)d_in[0];
    const void*  edges = d_in[1];

    int wbase = 2;
    if (n_in >= 9 && in_sizes[2] <= 1) wbase = 3;
    const float* W1 = (const float*)d_in[wbase + 0];
    const float* b1 = (const float*)d_in[wbase + 1];
    const float* W2 = (const float*)d_in[wbase + 2];
    const float* b2 = (const float*)d_in[wbase + 3];
    const float* W3 = (const float*)d_in[wbase + 4];
    const float* b3 = (const float*)d_in[wbase + 5];
    float* out = (float*)d_out;

    int N = in_sizes[0] / IN_F;
    int E = in_sizes[1] / 2;
    if (N > N_NODES_MAX) N = N_NODES_MAX;
    if (E > N_EDGES_MAX) E = N_EDGES_MAX;

    int scanBlocks = (N + 255) / 256;

    // dtype detect + CSR build + weight conversion (independent of CSR)
    detect_dtype_kernel<<<1, 256>>>((const int*)edges, E);
    zero_deg_kernel<<<(N + 255) / 256, 256>>>(N);
    conv_w_kernel<1><<<(HID * IN_F + 255) / 256, 256>>>(W1, HID * IN_F);
    conv_w_kernel<2><<<(HID2 * HID + 255) / 256, 256>>>(W2, HID2 * HID);
    hist_kernel<<<(E + 255) / 256, 256>>>(edges, E, N);
    scan_partial_kernel<<<scanBlocks, 256>>>(N);
    scan_blocksums_kernel<<<1, 256>>>(scanBlocks);
    scan_final_kernel<<<scanBlocks, 256>>>(N);
    scatter_kernel<<<(E + 255) / 256, 256>>>(edges, E, N);

    const int warpsPerBlock = 8;
    int aggBlocks = (N + warpsPerBlock - 1) / warpsPerBlock;

    // layer 1: agg(x) -> aggh/aggl ; mma-gemm -> g_h1 (ReLU)
    agg_kernel<IN_F, true><<<aggBlocks, warpsPerBlock * 32>>>(x, N);
    {
        dim3 grid(HID / 64, (N + 127) / 128);
        gemm_mma_kernel<IN_F, 1><<<grid, 256>>>(b1, N, HID);
    }
    // layer 2: agg(g_h1) -> aggh/aggl ; mma-gemm -> g_h2 (ReLU)
    agg_kernel<HID, false><<<aggBlocks, warpsPerBlock * 32>>>(x, N);
    {
        dim3 grid(HID2 / 64, (N + 127) / 128);
        gemm_mma_kernel<HID, 2><<<grid, 256>>>(b2, N, HID2);
    }
    // head
    head_kernel<<<(N + 127) / 128, 128>>>(W3, b3, out, N);
}

// round 13
// speedup vs baseline: 1.4219x; 1.0983x over previous
#include <cuda_runtime.h>
#include <cuda_bf16.h>
#include <stdint.h>

// Problem constants (fixed by the dataset)
#define N_NODES_MAX 50000
#define N_EDGES_MAX 800000
#define IN_F   128
#define HID    256
#define HID2   128
#define N_CLS  2

// ---------------- scratch (static device globals; no allocation) -------------
__device__ int   g_i64;
__device__ int   g_deg[N_NODES_MAX];
__device__ int   g_off[N_NODES_MAX + 1];
__device__ int   g_cursor[N_NODES_MAX];
__device__ int   g_part[256];
__device__ int   g_partoff[256];
__device__ __align__(16) float g_deginv[N_NODES_MAX];
__device__ __align__(16) int   g_src[N_EDGES_MAX];
// bf16 split planes of agg(x) [N,128]
__device__ __align__(16) __nv_bfloat16 g_aggh[(size_t)N_NODES_MAX * IN_F];
__device__ __align__(16) __nv_bfloat16 g_aggl[(size_t)N_NODES_MAX * IN_F];
// h1 = relu(agg(x)@W1+b1) stored as bf16 split planes [N,256]
__device__ __align__(16) __nv_bfloat16 g_h1h[(size_t)N_NODES_MAX * HID];
__device__ __align__(16) __nv_bfloat16 g_h1l[(size_t)N_NODES_MAX * HID];
// t = h1 @ W2^T (no bias/relu) [N,128] fp32
__device__ __align__(16) float g_t[(size_t)N_NODES_MAX * HID2];
// split-precision weights
__device__ __align__(16) __nv_bfloat16 g_w1h[HID * IN_F],  g_w1l[HID * IN_F];
__device__ __align__(16) __nv_bfloat16 g_w2h[HID2 * HID],  g_w2l[HID2 * HID];

__device__ __forceinline__ void f4_acc(float4& a, const float4& v) {
    a.x += v.x; a.y += v.y; a.z += v.z; a.w += v.w;
}

__device__ __forceinline__ uint32_t pack_bf2(float a, float b) {
    __nv_bfloat162 v = __floats2bfloat162_rn(a, b);
    return *(uint32_t*)&v;
}

__device__ __forceinline__ int edge_at(const void* edges, int E, int which, int e) {
    if (g_i64) {
        const long long* p = (const long long*)edges;
        return (int)p[(size_t)which * E + e];
    } else {
        const int* p = (const int*)edges;
        return p[(size_t)which * E + e];
    }
}

// ---------------- dtype detect -----------------------------------------------
__global__ void detect_dtype_kernel(const int* __restrict__ raw, int E) {
    __shared__ int nz;
    if (threadIdx.x == 0) nz = 0;
    __syncthreads();
    int samples = min(1024, E);
    for (int i = threadIdx.x; i < samples; i += blockDim.x) {
        if (raw[2 * i + 1] != 0) atomicOr(&nz, 1);
    }
    __syncthreads();
    if (threadIdx.x == 0) g_i64 = (nz == 0) ? 1 : 0;
}

// ---------------- CSR build --------------------------------------------------
__global__ void zero_deg_kernel(int n) {
    int i = blockIdx.x * blockDim.x + threadIdx.x;
    if (i < n) g_deg[i] = 0;
}

__global__ void hist_kernel(const void* __restrict__ edges, int E, int n) {
    int e = blockIdx.x * blockDim.x + threadIdx.x;
    if (e < E) {
        int d = edge_at(edges, E, 1, e);
        d = max(0, min(d, n - 1));
        atomicAdd(&g_deg[d], 1);
    }
}

__global__ void scan_partial_kernel(int n) {
    __shared__ int s[256];
    int b = blockIdx.x, t = threadIdx.x;
    int i = b * 256 + t;
    s[t] = (i < n) ? g_deg[i] : 0;
    __syncthreads();
    #pragma unroll
    for (int off = 128; off > 0; off >>= 1) {
        if (t < off) s[t] += s[t + off];
        __syncthreads();
    }
    if (t == 0) g_part[b] = s[0];
}

__global__ void scan_blocksums_kernel(int nb) {
    __shared__ int s[256];
    int t = threadIdx.x;
    int v = (t < nb) ? g_part[t] : 0;
    s[t] = v;
    __syncthreads();
    #pragma unroll
    for (int off = 1; off < 256; off <<= 1) {
        int u = (t >= off) ? s[t - off] : 0;
        __syncthreads();
        s[t] += u;
        __syncthreads();
    }
    if (t < nb) g_partoff[t] = s[t] - v;
}

__global__ void scan_final_kernel(int n) {
    __shared__ int s[256];
    int b = blockIdx.x, t = threadIdx.x;
    int i = b * 256 + t;
    int d = (i < n) ? g_deg[i] : 0;
    s[t] = d;
    __syncthreads();
    #pragma unroll
    for (int off = 1; off < 256; off <<= 1) {
        int u = (t >= off) ? s[t - off] : 0;
        __syncthreads();
        s[t] += u;
        __syncthreads();
    }
    int base = g_partoff[b];
    if (i < n) {
        int excl = base + s[t] - d;
        g_off[i]    = excl;
        g_cursor[i] = excl;
        g_deginv[i] = 1.0f / fmaxf((float)d, 1.0f);
        if (i == n - 1) g_off[n] = excl + d;
    }
}

__global__ void scatter_kernel(const void* __restrict__ edges, int E, int n) {
    int e = blockIdx.x * blockDim.x + threadIdx.x;
    if (e < E) {
        int d = edge_at(edges, E, 1, e);
        d = max(0, min(d, n - 1));
        int s = edge_at(edges, E, 0, e);
        s = max(0, min(s, n - 1));
        int p = atomicAdd(&g_cursor[d], 1);
        if (p >= 0 && p < N_EDGES_MAX) g_src[p] = s;
    }
}

// ---------------- weight split conversion ------------------------------------
template <int WHICH>
__global__ void conv_w_kernel(const float* __restrict__ W, int n) {
    int i = blockIdx.x * blockDim.x + threadIdx.x;
    if (i >= n) return;
    float w = W[i];
    __nv_bfloat16 h = __float2bfloat16(w);
    __nv_bfloat16 l = __float2bfloat16(w - __bfloat162float(h));
    if (WHICH == 1) { g_w1h[i] = h; g_w1l[i] = l; }
    else            { g_w2h[i] = h; g_w2l[i] = l; }
}

// ------- agg1: warp/node gather of x (128-wide) -> bf16 split planes ----------
__global__ void agg1_kernel(const float* __restrict__ x, int M) {
    int gw   = (blockIdx.x * blockDim.x + threadIdx.x) >> 5;
    int lane = threadIdx.x & 31;
    if (gw >= M) return;
    int beg = g_off[gw];
    int end = g_off[gw + 1];

    float4 acc = make_float4(0.f, 0.f, 0.f, 0.f);
    int i = beg;
    for (; i + 3 < end; i += 4) {
        int s0 = g_src[i], s1 = g_src[i + 1], s2 = g_src[i + 2], s3 = g_src[i + 3];
        float4 v0 = ((const float4*)(x + (size_t)s0 * IN_F))[lane];
        float4 v1 = ((const float4*)(x + (size_t)s1 * IN_F))[lane];
        float4 v2 = ((const float4*)(x + (size_t)s2 * IN_F))[lane];
        float4 v3 = ((const float4*)(x + (size_t)s3 * IN_F))[lane];
        f4_acc(acc, v0); f4_acc(acc, v1); f4_acc(acc, v2); f4_acc(acc, v3);
    }
    for (; i < end; ++i) {
        int s0 = g_src[i];
        f4_acc(acc, ((const float4*)(x + (size_t)s0 * IN_F))[lane]);
    }

    float dinv = g_deginv[gw];
    float vx = acc.x * dinv, vy = acc.y * dinv, vz = acc.z * dinv, vw = acc.w * dinv;
    float hx = __bfloat162float(__float2bfloat16(vx));
    float hy = __bfloat162float(__float2bfloat16(vy));
    float hz = __bfloat162float(__float2bfloat16(vz));
    float hw = __bfloat162float(__float2bfloat16(vw));
    size_t idx = (size_t)gw * IN_F + lane * 4;
    *(uint2*)&g_aggh[idx] = make_uint2(pack_bf2(hx, hy), pack_bf2(hz, hw));
    *(uint2*)&g_aggl[idx] = make_uint2(pack_bf2(vx - hx, vy - hy), pack_bf2(vz - hz, vw - hw));
}

// ---------------- bf16 split-precision tensor-core GEMM -----------------------
// OUT=1: C = relu(aggA @ W1^T + b1) stored as bf16 split planes (h1h/h1l), N=256
// OUT=2: C = h1 @ W2^T (raw fp32, no bias/relu) -> g_t, N=128
#define SMP 40   // smem row pitch in bf16

__device__ __forceinline__ void mma_bf16(float* c, const uint32_t* a, const uint32_t* b) {
    asm volatile(
        "mma.sync.aligned.m16n8k16.row.col.f32.bf16.bf16.f32 "
        "{%0,%1,%2,%3}, {%4,%5,%6,%7}, {%8,%9}, {%0,%1,%2,%3};"
        : "+f"(c[0]), "+f"(c[1]), "+f"(c[2]), "+f"(c[3])
        : "r"(a[0]), "r"(a[1]), "r"(a[2]), "r"(a[3]), "r"(b[0]), "r"(b[1]));
}

__device__ __forceinline__ uint32_t lds_b32(const __nv_bfloat16* s, int row, int colb32) {
    return *(const uint32_t*)&s[row * SMP + colb32 * 2];
}

template <int K, int OUT>
__global__ void gemm_mma_kernel(const float* __restrict__ bias, int M, int N) {
    const __nv_bfloat16* __restrict__ Ah = (OUT == 1) ? g_aggh : g_h1h;
    const __nv_bfloat16* __restrict__ Al = (OUT == 1) ? g_aggl : g_h1l;
    const __nv_bfloat16* __restrict__ Wh = (OUT == 1) ? g_w1h : g_w2h;
    const __nv_bfloat16* __restrict__ Wl = (OUT == 1) ? g_w1l : g_w2l;

    __shared__ __align__(16) __nv_bfloat16 sAh[128 * SMP];
    __shared__ __align__(16) __nv_bfloat16 sAl[128 * SMP];
    __shared__ __align__(16) __nv_bfloat16 sBh[64 * SMP];
    __shared__ __align__(16) __nv_bfloat16 sBl[64 * SMP];

    int tid  = threadIdx.x;
    int wid  = tid >> 5;
    int lane = tid & 31;
    int g    = lane >> 2;
    int t    = lane & 3;
    int warpM = wid >> 1;
    int warpN = wid & 1;
    int m0 = blockIdx.y * 128;
    int n0 = blockIdx.x * 64;

    float c[2][4][4];
    #pragma unroll
    for (int mi = 0; mi < 2; ++mi)
        #pragma unroll
        for (int ni = 0; ni < 4; ++ni)
            #pragma unroll
            for (int j = 0; j < 4; ++j) c[mi][ni][j] = 0.f;

    int arow = tid >> 1, aseg = tid & 1;
    int brow = tid >> 2, bseg = tid & 3;

    for (int k0 = 0; k0 < K; k0 += 32) {
        {
            int m = m0 + arow;
            uint4 z = make_uint4(0, 0, 0, 0);
            uint4 h0 = z, h1 = z, l0 = z, l1 = z;
            if (m < M) {
                size_t go = (size_t)m * K + k0 + aseg * 16;
                h0 = *(const uint4*)&Ah[go];
                h1 = *(const uint4*)&Ah[go + 8];
                l0 = *(const uint4*)&Al[go];
                l1 = *(const uint4*)&Al[go + 8];
            }
            int so = arow * SMP + aseg * 16;
            *(uint4*)&sAh[so] = h0; *(uint4*)&sAh[so + 8] = h1;
            *(uint4*)&sAl[so] = l0; *(uint4*)&sAl[so + 8] = l1;
        }
        {
            size_t go = (size_t)(n0 + brow) * K + k0 + bseg * 8;
            int so = brow * SMP + bseg * 8;
            *(uint4*)&sBh[so] = *(const uint4*)&Wh[go];
            *(uint4*)&sBl[so] = *(const uint4*)&Wl[go];
        }
        __syncthreads();

        #pragma unroll
        for (int ks = 0; ks < 32; ks += 16) {
            int koff = ks >> 1;
            uint32_t ah[2][4], al[2][4];
            #pragma unroll
            for (int mi = 0; mi < 2; ++mi) {
                int rb = warpM * 32 + mi * 16;
                ah[mi][0] = lds_b32(sAh, rb + g,     koff + t);
                ah[mi][1] = lds_b32(sAh, rb + g + 8, koff + t);
                ah[mi][2] = lds_b32(sAh, rb + g,     koff + t + 4);
                ah[mi][3] = lds_b32(sAh, rb + g + 8, koff + t + 4);
                al[mi][0] = lds_b32(sAl, rb + g,     koff + t);
                al[mi][1] = lds_b32(sAl, rb + g + 8, koff + t);
                al[mi][2] = lds_b32(sAl, rb + g,     koff + t + 4);
                al[mi][3] = lds_b32(sAl, rb + g + 8, koff + t + 4);
            }
            uint32_t bh[4][2], bl[4][2];
            #pragma unroll
            for (int ni = 0; ni < 4; ++ni) {
                int nb = warpN * 32 + ni * 8;
                bh[ni][0] = lds_b32(sBh, nb + g, koff + t);
                bh[ni][1] = lds_b32(sBh, nb + g, koff + t + 4);
                bl[ni][0] = lds_b32(sBl, nb + g, koff + t);
                bl[ni][1] = lds_b32(sBl, nb + g, koff + t + 4);
            }
            #pragma unroll
            for (int mi = 0; mi < 2; ++mi)
                #pragma unroll
                for (int ni = 0; ni < 4; ++ni) {
                    mma_bf16(c[mi][ni], ah[mi], bh[ni]);
                    mma_bf16(c[mi][ni], ah[mi], bl[ni]);
                    mma_bf16(c[mi][ni], al[mi], bh[ni]);
                }
        }
        __syncthreads();
    }

    #pragma unroll
    for (int mi = 0; mi < 2; ++mi) {
        int row0 = m0 + warpM * 32 + mi * 16 + g;
        int row1 = row0 + 8;
        #pragma unroll
        for (int ni = 0; ni < 4; ++ni) {
            int col = n0 + warpN * 32 + ni * 8 + 2 * t;
            if (OUT == 1) {
                float b0 = bias[col], b1 = bias[col + 1];
                if (row0 < M) {
                    float v0 = fmaxf(c[mi][ni][0] + b0, 0.f);
                    float v1 = fmaxf(c[mi][ni][1] + b1, 0.f);
                    float h0 = __bfloat162float(__float2bfloat16(v0));
                    float h1 = __bfloat162float(__float2bfloat16(v1));
                    size_t o = (size_t)row0 * N + col;
                    *(uint32_t*)&g_h1h[o] = pack_bf2(h0, h1);
                    *(uint32_t*)&g_h1l[o] = pack_bf2(v0 - h0, v1 - h1);
                }
                if (row1 < M) {
                    float v0 = fmaxf(c[mi][ni][2] + b0, 0.f);
                    float v1 = fmaxf(c[mi][ni][3] + b1, 0.f);
                    float h0 = __bfloat162float(__float2bfloat16(v0));
                    float h1 = __bfloat162float(__float2bfloat16(v1));
                    size_t o = (size_t)row1 * N + col;
                    *(uint32_t*)&g_h1h[o] = pack_bf2(h0, h1);
                    *(uint32_t*)&g_h1l[o] = pack_bf2(v0 - h0, v1 - h1);
                }
            } else {
                if (row0 < M)
                    *(float2*)&g_t[(size_t)row0 * N + col] =
                        make_float2(c[mi][ni][0], c[mi][ni][1]);
                if (row1 < M)
                    *(float2*)&g_t[(size_t)row1 * N + col] =
                        make_float2(c[mi][ni][2], c[mi][ni][3]);
            }
        }
    }
}

// ---- agg2 + head fused: h2 = relu(deginv*sum t[src] + b2); out = h2@W3^T+b3 --
__global__ void agg2_head_kernel(const float* __restrict__ b2,
                                 const float* __restrict__ W3,
                                 const float* __restrict__ b3,
                                 float* __restrict__ out, int M) {
    int gw   = (blockIdx.x * blockDim.x + threadIdx.x) >> 5;
    int lane = threadIdx.x & 31;
    if (gw >= M) return;
    int beg = g_off[gw];
    int end = g_off[gw + 1];

    float4 acc = make_float4(0.f, 0.f, 0.f, 0.f);
    int i = beg;
    for (; i + 3 < end; i += 4) {
        int s0 = g_src[i], s1 = g_src[i + 1], s2 = g_src[i + 2], s3 = g_src[i + 3];
        float4 v0 = ((const float4*)(g_t + (size_t)s0 * HID2))[lane];
        float4 v1 = ((const float4*)(g_t + (size_t)s1 * HID2))[lane];
        float4 v2 = ((const float4*)(g_t + (size_t)s2 * HID2))[lane];
        float4 v3 = ((const float4*)(g_t + (size_t)s3 * HID2))[lane];
        f4_acc(acc, v0); f4_acc(acc, v1); f4_acc(acc, v2); f4_acc(acc, v3);
    }
    for (; i < end; ++i) {
        int s0 = g_src[i];
        f4_acc(acc, ((const float4*)(g_t + (size_t)s0 * HID2))[lane]);
    }

    float dinv = g_deginv[gw];
    float4 bb = ((const float4*)b2)[lane];
    float4 h2;
    h2.x = fmaxf(acc.x * dinv + bb.x, 0.f);
    h2.y = fmaxf(acc.y * dinv + bb.y, 0.f);
    h2.z = fmaxf(acc.z * dinv + bb.z, 0.f);
    h2.w = fmaxf(acc.w * dinv + bb.w, 0.f);

    float4 w0 = ((const float4*)W3)[lane];            // W3 row 0
    float4 w1 = ((const float4*)(W3 + HID2))[lane];   // W3 row 1
    float s0 = h2.x * w0.x + h2.y * w0.y + h2.z * w0.z + h2.w * w0.w;
    float s1 = h2.x * w1.x + h2.y * w1.y + h2.z * w1.z + h2.w * w1.w;
    #pragma unroll
    for (int off = 16; off > 0; off >>= 1) {
        s0 += __shfl_xor_sync(0xffffffffu, s0, off);
        s1 += __shfl_xor_sync(0xffffffffu, s1, off);
    }
    if (lane == 0) {
        out[(size_t)gw * 2 + 0] = s0 + b3[0];
        out[(size_t)gw * 2 + 1] = s1 + b3[1];
    }
}

// ---------------- launch -----------------------------------------------------
extern "C" void kernel_launch(void* const* d_in, const int* in_sizes, int n_in,
                              void* d_out, int out_size) {
    const float* x     = (const float*)d_in[0];
    const void*  edges = d_in[1];

    int wbase = 2;
    if (n_in >= 9 && in_sizes[2] <= 1) wbase = 3;
    const float* W1 = (const float*)d_in[wbase + 0];
    const float* b1 = (const float*)d_in[wbase + 1];
    const float* W2 = (const float*)d_in[wbase + 2];
    const float* b2 = (const float*)d_in[wbase + 3];
    const float* W3 = (const float*)d_in[wbase + 4];
    const float* b3 = (const float*)d_in[wbase + 5];
    float* out = (float*)d_out;

    int N = in_sizes[0] / IN_F;
    int E = in_sizes[1] / 2;
    if (N > N_NODES_MAX) N = N_NODES_MAX;
    if (E > N_EDGES_MAX) E = N_EDGES_MAX;

    int scanBlocks = (N + 255) / 256;

    detect_dtype_kernel<<<1, 256>>>((const int*)edges, E);
    zero_deg_kernel<<<(N + 255) / 256, 256>>>(N);
    conv_w_kernel<1><<<(HID * IN_F + 255) / 256, 256>>>(W1, HID * IN_F);
    conv_w_kernel<2><<<(HID2 * HID + 255) / 256, 256>>>(W2, HID2 * HID);
    hist_kernel<<<(E + 255) / 256, 256>>>(edges, E, N);
    scan_partial_kernel<<<scanBlocks, 256>>>(N);
    scan_blocksums_kernel<<<1, 256>>>(scanBlocks);
    scan_final_kernel<<<scanBlocks, 256>>>(N);
    scatter_kernel<<<(E + 255) / 256, 256>>>(edges, E, N);

    const int warpsPerBlock = 8;
    int aggBlocks = (N + warpsPerBlock - 1) / warpsPerBlock;

    // layer 1: agg(x) -> planes ; mma-gemm (+bias+relu) -> h1 bf16 planes
    agg1_kernel<<<aggBlocks, warpsPerBlock * 32>>>(x, N);
    {
        dim3 grid(HID / 64, (N + 127) / 128);
        gemm_mma_kernel<IN_F, 1><<<grid, 256>>>(b1, N, HID);
    }
    // layer 2 (reordered): t = h1 @ W2^T ; then agg+bias+relu+head fused
    {
        dim3 grid(HID2 / 64, (N + 127) / 128);
        gemm_mma_kernel<HID, 2><<<grid, 256>>>(nullptr, N, HID2);
    }
    agg2_head_kernel<<<aggBlocks, warpsPerBlock * 32>>>(b2, W3, b3, out, N);
}

// round 14
// speedup vs baseline: 1.4998x; 1.0548x over previous
#include <cuda_runtime.h>
#include <cuda_bf16.h>
#include <cuda_fp16.h>
#include <stdint.h>

// Problem constants (fixed by the dataset)
#define N_NODES_MAX 50000
#define N_EDGES_MAX 800000
#define IN_F   128
#define HID    256
#define HID2   128
#define N_CLS  2

// ---------------- scratch (static device globals; no allocation) -------------
__device__ int   g_i64;
__device__ int   g_deg[N_NODES_MAX];
__device__ int   g_off[N_NODES_MAX + 1];
__device__ int   g_cursor[N_NODES_MAX];
__device__ int   g_part[256];
__device__ int   g_partoff[256];
__device__ __align__(16) float g_deginv[N_NODES_MAX];
__device__ __align__(16) int   g_src[N_EDGES_MAX];
// bf16 split planes of agg(x) [N,128]
__device__ __align__(16) __nv_bfloat16 g_aggh[(size_t)N_NODES_MAX * IN_F];
__device__ __align__(16) __nv_bfloat16 g_aggl[(size_t)N_NODES_MAX * IN_F];
// h1 = relu(agg(x)@W1+b1) stored as bf16 split planes [N,256]
__device__ __align__(16) __nv_bfloat16 g_h1h[(size_t)N_NODES_MAX * HID];
__device__ __align__(16) __nv_bfloat16 g_h1l[(size_t)N_NODES_MAX * HID];
// t = h1 @ W2^T (no bias/relu) [N,128] fp16 (halves agg2 gather bytes)
__device__ __align__(16) __half g_t[(size_t)N_NODES_MAX * HID2];
// split-precision weights
__device__ __align__(16) __nv_bfloat16 g_w1h[HID * IN_F],  g_w1l[HID * IN_F];
__device__ __align__(16) __nv_bfloat16 g_w2h[HID2 * HID],  g_w2l[HID2 * HID];

__device__ __forceinline__ void f4_acc(float4& a, const float4& v) {
    a.x += v.x; a.y += v.y; a.z += v.z; a.w += v.w;
}

__device__ __forceinline__ uint32_t pack_bf2(float a, float b) {
    __nv_bfloat162 v = __floats2bfloat162_rn(a, b);
    return *(uint32_t*)&v;
}

__device__ __forceinline__ int edge_at(const void* edges, int E, int which, int e) {
    if (g_i64) {
        const long long* p = (const long long*)edges;
        return (int)p[(size_t)which * E + e];
    } else {
        const int* p = (const int*)edges;
        return p[(size_t)which * E + e];
    }
}

// ---------------- dtype detect -----------------------------------------------
__global__ void detect_dtype_kernel(const int* __restrict__ raw, int E) {
    __shared__ int nz;
    if (threadIdx.x == 0) nz = 0;
    __syncthreads();
    int samples = min(1024, E);
    for (int i = threadIdx.x; i < samples; i += blockDim.x) {
        if (raw[2 * i + 1] != 0) atomicOr(&nz, 1);
    }
    __syncthreads();
    if (threadIdx.x == 0) g_i64 = (nz == 0) ? 1 : 0;
}

// ---------------- CSR build --------------------------------------------------
__global__ void zero_deg_kernel(int n) {
    int i = blockIdx.x * blockDim.x + threadIdx.x;
    if (i < n) g_deg[i] = 0;
}

__global__ void hist_kernel(const void* __restrict__ edges, int E, int n) {
    int e = blockIdx.x * blockDim.x + threadIdx.x;
    if (e < E) {
        int d = edge_at(edges, E, 1, e);
        d = max(0, min(d, n - 1));
        atomicAdd(&g_deg[d], 1);
    }
}

__global__ void scan_partial_kernel(int n) {
    __shared__ int s[256];
    int b = blockIdx.x, t = threadIdx.x;
    int i = b * 256 + t;
    s[t] = (i < n) ? g_deg[i] : 0;
    __syncthreads();
    #pragma unroll
    for (int off = 128; off > 0; off >>= 1) {
        if (t < off) s[t] += s[t + off];
        __syncthreads();
    }
    if (t == 0) g_part[b] = s[0];
}

__global__ void scan_blocksums_kernel(int nb) {
    __shared__ int s[256];
    int t = threadIdx.x;
    int v = (t < nb) ? g_part[t] : 0;
    s[t] = v;
    __syncthreads();
    #pragma unroll
    for (int off = 1; off < 256; off <<= 1) {
        int u = (t >= off) ? s[t - off] : 0;
        __syncthreads();
        s[t] += u;
        __syncthreads();
    }
    if (t < nb) g_partoff[t] = s[t] - v;
}

__global__ void scan_final_kernel(int n) {
    __shared__ int s[256];
    int b = blockIdx.x, t = threadIdx.x;
    int i = b * 256 + t;
    int d = (i < n) ? g_deg[i] : 0;
    s[t] = d;
    __syncthreads();
    #pragma unroll
    for (int off = 1; off < 256; off <<= 1) {
        int u = (t >= off) ? s[t - off] : 0;
        __syncthreads();
        s[t] += u;
        __syncthreads();
    }
    int base = g_partoff[b];
    if (i < n) {
        int excl = base + s[t] - d;
        g_off[i]    = excl;
        g_cursor[i] = excl;
        g_deginv[i] = 1.0f / fmaxf((float)d, 1.0f);
        if (i == n - 1) g_off[n] = excl + d;
    }
}

__global__ void scatter_kernel(const void* __restrict__ edges, int E, int n) {
    int e = blockIdx.x * blockDim.x + threadIdx.x;
    if (e < E) {
        int d = edge_at(edges, E, 1, e);
        d = max(0, min(d, n - 1));
        int s = edge_at(edges, E, 0, e);
        s = max(0, min(s, n - 1));
        int p = atomicAdd(&g_cursor[d], 1);
        if (p >= 0 && p < N_EDGES_MAX) g_src[p] = s;
    }
}

// ---------------- weight split conversion ------------------------------------
template <int WHICH>
__global__ void conv_w_kernel(const float* __restrict__ W, int n) {
    int i = blockIdx.x * blockDim.x + threadIdx.x;
    if (i >= n) return;
    float w = W[i];
    __nv_bfloat16 h = __float2bfloat16(w);
    __nv_bfloat16 l = __float2bfloat16(w - __bfloat162float(h));
    if (WHICH == 1) { g_w1h[i] = h; g_w1l[i] = l; }
    else            { g_w2h[i] = h; g_w2l[i] = l; }
}

// ------- agg1: warp/node gather of x (128-wide) -> bf16 split planes ----------
__global__ void agg1_kernel(const float* __restrict__ x, int M) {
    int gw   = (blockIdx.x * blockDim.x + threadIdx.x) >> 5;
    int lane = threadIdx.x & 31;
    if (gw >= M) return;
    int beg = g_off[gw];
    int end = g_off[gw + 1];

    float4 acc = make_float4(0.f, 0.f, 0.f, 0.f);
    int i = beg;
    for (; i + 3 < end; i += 4) {
        int s0 = g_src[i], s1 = g_src[i + 1], s2 = g_src[i + 2], s3 = g_src[i + 3];
        float4 v0 = ((const float4*)(x + (size_t)s0 * IN_F))[lane];
        float4 v1 = ((const float4*)(x + (size_t)s1 * IN_F))[lane];
        float4 v2 = ((const float4*)(x + (size_t)s2 * IN_F))[lane];
        float4 v3 = ((const float4*)(x + (size_t)s3 * IN_F))[lane];
        f4_acc(acc, v0); f4_acc(acc, v1); f4_acc(acc, v2); f4_acc(acc, v3);
    }
    for (; i < end; ++i) {
        int s0 = g_src[i];
        f4_acc(acc, ((const float4*)(x + (size_t)s0 * IN_F))[lane]);
    }

    float dinv = g_deginv[gw];
    float vx = acc.x * dinv, vy = acc.y * dinv, vz = acc.z * dinv, vw = acc.w * dinv;
    float hx = __bfloat162float(__float2bfloat16(vx));
    float hy = __bfloat162float(__float2bfloat16(vy));
    float hz = __bfloat162float(__float2bfloat16(vz));
    float hw = __bfloat162float(__float2bfloat16(vw));
    size_t idx = (size_t)gw * IN_F + lane * 4;
    *(uint2*)&g_aggh[idx] = make_uint2(pack_bf2(hx, hy), pack_bf2(hz, hw));
    *(uint2*)&g_aggl[idx] = make_uint2(pack_bf2(vx - hx, vy - hy), pack_bf2(vz - hz, vw - hw));
}

// ---------------- bf16 split-precision tensor-core GEMM -----------------------
// OUT=1: C = relu(aggA @ W1^T + b1) stored as bf16 split planes (h1h/h1l), N=256
// OUT=2: C = h1 @ W2^T (raw, no bias/relu) -> g_t as fp16, N=128
#define SMP 40   // smem row pitch in bf16

__device__ __forceinline__ void mma_bf16(float* c, const uint32_t* a, const uint32_t* b) {
    asm volatile(
        "mma.sync.aligned.m16n8k16.row.col.f32.bf16.bf16.f32 "
        "{%0,%1,%2,%3}, {%4,%5,%6,%7}, {%8,%9}, {%0,%1,%2,%3};"
        : "+f"(c[0]), "+f"(c[1]), "+f"(c[2]), "+f"(c[3])
        : "r"(a[0]), "r"(a[1]), "r"(a[2]), "r"(a[3]), "r"(b[0]), "r"(b[1]));
}

__device__ __forceinline__ uint32_t lds_b32(const __nv_bfloat16* s, int row, int colb32) {
    return *(const uint32_t*)&s[row * SMP + colb32 * 2];
}

template <int K, int OUT>
__global__ void gemm_mma_kernel(const float* __restrict__ bias, int M, int N) {
    const __nv_bfloat16* __restrict__ Ah = (OUT == 1) ? g_aggh : g_h1h;
    const __nv_bfloat16* __restrict__ Al = (OUT == 1) ? g_aggl : g_h1l;
    const __nv_bfloat16* __restrict__ Wh = (OUT == 1) ? g_w1h : g_w2h;
    const __nv_bfloat16* __restrict__ Wl = (OUT == 1) ? g_w1l : g_w2l;

    __shared__ __align__(16) __nv_bfloat16 sAh[128 * SMP];
    __shared__ __align__(16) __nv_bfloat16 sAl[128 * SMP];
    __shared__ __align__(16) __nv_bfloat16 sBh[64 * SMP];
    __shared__ __align__(16) __nv_bfloat16 sBl[64 * SMP];

    int tid  = threadIdx.x;
    int wid  = tid >> 5;
    int lane = tid & 31;
    int g    = lane >> 2;
    int t    = lane & 3;
    int warpM = wid >> 1;
    int warpN = wid & 1;
    int m0 = blockIdx.y * 128;
    int n0 = blockIdx.x * 64;

    float c[2][4][4];
    #pragma unroll
    for (int mi = 0; mi < 2; ++mi)
        #pragma unroll
        for (int ni = 0; ni < 4; ++ni)
            #pragma unroll
            for (int j = 0; j < 4; ++j) c[mi][ni][j] = 0.f;

    int arow = tid >> 1, aseg = tid & 1;
    int brow = tid >> 2, bseg = tid & 3;

    for (int k0 = 0; k0 < K; k0 += 32) {
        {
            int m = m0 + arow;
            uint4 z = make_uint4(0, 0, 0, 0);
            uint4 h0 = z, h1 = z, l0 = z, l1 = z;
            if (m < M) {
                size_t go = (size_t)m * K + k0 + aseg * 16;
                h0 = *(const uint4*)&Ah[go];
                h1 = *(const uint4*)&Ah[go + 8];
                l0 = *(const uint4*)&Al[go];
                l1 = *(const uint4*)&Al[go + 8];
            }
            int so = arow * SMP + aseg * 16;
            *(uint4*)&sAh[so] = h0; *(uint4*)&sAh[so + 8] = h1;
            *(uint4*)&sAl[so] = l0; *(uint4*)&sAl[so + 8] = l1;
        }
        {
            size_t go = (size_t)(n0 + brow) * K + k0 + bseg * 8;
            int so = brow * SMP + bseg * 8;
            *(uint4*)&sBh[so] = *(const uint4*)&Wh[go];
            *(uint4*)&sBl[so] = *(const uint4*)&Wl[go];
        }
        __syncthreads();

        #pragma unroll
        for (int ks = 0; ks < 32; ks += 16) {
            int koff = ks >> 1;
            uint32_t ah[2][4], al[2][4];
            #pragma unroll
            for (int mi = 0; mi < 2; ++mi) {
                int rb = warpM * 32 + mi * 16;
                ah[mi][0] = lds_b32(sAh, rb + g,     koff + t);
                ah[mi][1] = lds_b32(sAh, rb + g + 8, koff + t);
                ah[mi][2] = lds_b32(sAh, rb + g,     koff + t + 4);
                ah[mi][3] = lds_b32(sAh, rb + g + 8, koff + t + 4);
                al[mi][0] = lds_b32(sAl, rb + g,     koff + t);
                al[mi][1] = lds_b32(sAl, rb + g + 8, koff + t);
                al[mi][2] = lds_b32(sAl, rb + g,     koff + t + 4);
                al[mi][3] = lds_b32(sAl, rb + g + 8, koff + t + 4);
            }
            uint32_t bh[4][2], bl[4][2];
            #pragma unroll
            for (int ni = 0; ni < 4; ++ni) {
                int nb = warpN * 32 + ni * 8;
                bh[ni][0] = lds_b32(sBh, nb + g, koff + t);
                bh[ni][1] = lds_b32(sBh, nb + g, koff + t + 4);
                bl[ni][0] = lds_b32(sBl, nb + g, koff + t);
                bl[ni][1] = lds_b32(sBl, nb + g, koff + t + 4);
            }
            #pragma unroll
            for (int mi = 0; mi < 2; ++mi)
                #pragma unroll
                for (int ni = 0; ni < 4; ++ni) {
                    mma_bf16(c[mi][ni], ah[mi], bh[ni]);
                    mma_bf16(c[mi][ni], ah[mi], bl[ni]);
                    mma_bf16(c[mi][ni], al[mi], bh[ni]);
                }
        }
        __syncthreads();
    }

    #pragma unroll
    for (int mi = 0; mi < 2; ++mi) {
        int row0 = m0 + warpM * 32 + mi * 16 + g;
        int row1 = row0 + 8;
        #pragma unroll
        for (int ni = 0; ni < 4; ++ni) {
            int col = n0 + warpN * 32 + ni * 8 + 2 * t;
            if (OUT == 1) {
                float b0 = bias[col], b1 = bias[col + 1];
                if (row0 < M) {
                    float v0 = fmaxf(c[mi][ni][0] + b0, 0.f);
                    float v1 = fmaxf(c[mi][ni][1] + b1, 0.f);
                    float h0 = __bfloat162float(__float2bfloat16(v0));
                    float h1 = __bfloat162float(__float2bfloat16(v1));
                    size_t o = (size_t)row0 * N + col;
                    *(uint32_t*)&g_h1h[o] = pack_bf2(h0, h1);
                    *(uint32_t*)&g_h1l[o] = pack_bf2(v0 - h0, v1 - h1);
                }
                if (row1 < M) {
                    float v0 = fmaxf(c[mi][ni][2] + b0, 0.f);
                    float v1 = fmaxf(c[mi][ni][3] + b1, 0.f);
                    float h0 = __bfloat162float(__float2bfloat16(v0));
                    float h1 = __bfloat162float(__float2bfloat16(v1));
                    size_t o = (size_t)row1 * N + col;
                    *(uint32_t*)&g_h1h[o] = pack_bf2(h0, h1);
                    *(uint32_t*)&g_h1l[o] = pack_bf2(v0 - h0, v1 - h1);
                }
            } else {
                if (row0 < M)
                    *(__half2*)&g_t[(size_t)row0 * N + col] =
                        __floats2half2_rn(c[mi][ni][0], c[mi][ni][1]);
                if (row1 < M)
                    *(__half2*)&g_t[(size_t)row1 * N + col] =
                        __floats2half2_rn(c[mi][ni][2], c[mi][ni][3]);
            }
        }
    }
}

// ---- agg2 + head fused: h2 = relu(deginv*sum t[src] + b2); out = h2@W3^T+b3 --
// t rows are fp16 (256B): lane loads uint2 = 4 halves -> cols 4*lane..4*lane+3.
__global__ void agg2_head_kernel(const float* __restrict__ b2,
                                 const float* __restrict__ W3,
                                 const float* __restrict__ b3,
                                 float* __restrict__ out, int M) {
    int gw   = (blockIdx.x * blockDim.x + threadIdx.x) >> 5;
    int lane = threadIdx.x & 31;
    if (gw >= M) return;
    int beg = g_off[gw];
    int end = g_off[gw + 1];

    float4 acc = make_float4(0.f, 0.f, 0.f, 0.f);
    int i = beg;
    for (; i + 3 < end; i += 4) {
        int s0 = g_src[i], s1 = g_src[i + 1], s2 = g_src[i + 2], s3 = g_src[i + 3];
        uint2 u0 = ((const uint2*)(g_t + (size_t)s0 * HID2))[lane];
        uint2 u1 = ((const uint2*)(g_t + (size_t)s1 * HID2))[lane];
        uint2 u2 = ((const uint2*)(g_t + (size_t)s2 * HID2))[lane];
        uint2 u3 = ((const uint2*)(g_t + (size_t)s3 * HID2))[lane];
        #pragma unroll
        for (int j = 0; j < 4; ++j) {
            uint2 u = (j == 0) ? u0 : (j == 1) ? u1 : (j == 2) ? u2 : u3;
            float2 f0 = __half22float2(*(__half2*)&u.x);
            float2 f1 = __half22float2(*(__half2*)&u.y);
            acc.x += f0.x; acc.y += f0.y; acc.z += f1.x; acc.w += f1.y;
        }
    }
    for (; i < end; ++i) {
        int s0 = g_src[i];
        uint2 u = ((const uint2*)(g_t + (size_t)s0 * HID2))[lane];
        float2 f0 = __half22float2(*(__half2*)&u.x);
        float2 f1 = __half22float2(*(__half2*)&u.y);
        acc.x += f0.x; acc.y += f0.y; acc.z += f1.x; acc.w += f1.y;
    }

    float dinv = g_deginv[gw];
    float4 bb = ((const float4*)b2)[lane];
    float4 h2;
    h2.x = fmaxf(acc.x * dinv + bb.x, 0.f);
    h2.y = fmaxf(acc.y * dinv + bb.y, 0.f);
    h2.z = fmaxf(acc.z * dinv + bb.z, 0.f);
    h2.w = fmaxf(acc.w * dinv + bb.w, 0.f);

    float4 w0 = ((const float4*)W3)[lane];            // W3 row 0
    float4 w1 = ((const float4*)(W3 + HID2))[lane];   // W3 row 1
    float s0 = h2.x * w0.x + h2.y * w0.y + h2.z * w0.z + h2.w * w0.w;
    float s1 = h2.x * w1.x + h2.y * w1.y + h2.z * w1.z + h2.w * w1.w;
    #pragma unroll
    for (int off = 16; off > 0; off >>= 1) {
        s0 += __shfl_xor_sync(0xffffffffu, s0, off);
        s1 += __shfl_xor_sync(0xffffffffu, s1, off);
    }
    if (lane == 0) {
        out[(size_t)gw * 2 + 0] = s0 + b3[0];
        out[(size_t)gw * 2 + 1] = s1 + b3[1];
    }
}

// ---------------- launch -----------------------------------------------------
extern "C" void kernel_launch(void* const* d_in, const int* in_sizes, int n_in,
                              void* d_out, int out_size) {
    const float* x     = (const float*)d_in[0];
    const void*  edges = d_in[1];

    int wbase = 2;
    if (n_in >= 9 && in_sizes[2] <= 1) wbase = 3;
    const float* W1 = (const float*)d_in[wbase + 0];
    const float* b1 = (const float*)d_in[wbase + 1];
    const float* W2 = (const float*)d_in[wbase + 2];
    const float* b2 = (const float*)d_in[wbase + 3];
    const float* W3 = (const float*)d_in[wbase + 4];
    const float* b3 = (const float*)d_in[wbase + 5];
    float* out = (float*)d_out;

    int N = in_sizes[0] / IN_F;
    int E = in_sizes[1] / 2;
    if (N > N_NODES_MAX) N = N_NODES_MAX;
    if (E > N_EDGES_MAX) E = N_EDGES_MAX;

    int scanBlocks = (N + 255) / 256;

    detect_dtype_kernel<<<1, 256>>>((const int*)edges, E);
    zero_deg_kernel<<<(N + 255) / 256, 256>>>(N);
    conv_w_kernel<1><<<(HID * IN_F + 255) / 256, 256>>>(W1, HID * IN_F);
    conv_w_kernel<2><<<(HID2 * HID + 255) / 256, 256>>>(W2, HID2 * HID);
    hist_kernel<<<(E + 255) / 256, 256>>>(edges, E, N);
    scan_partial_kernel<<<scanBlocks, 256>>>(N);
    scan_blocksums_kernel<<<1, 256>>>(scanBlocks);
    scan_final_kernel<<<scanBlocks, 256>>>(N);
    scatter_kernel<<<(E + 255) / 256, 256>>>(edges, E, N);

    const int warpsPerBlock = 8;
    int aggBlocks = (N + warpsPerBlock - 1) / warpsPerBlock;

    // layer 1: agg(x) -> planes ; mma-gemm (+bias+relu) -> h1 bf16 planes
    agg1_kernel<<<aggBlocks, warpsPerBlock * 32>>>(x, N);
    {
        dim3 grid(HID / 64, (N + 127) / 128);
        gemm_mma_kernel<IN_F, 1><<<grid, 256>>>(b1, N, HID);
    }
    // layer 2 (reordered): t = h1 @ W2^T (fp16) ; then agg+bias+relu+head fused
    {
        dim3 grid(HID2 / 64, (N + 127) / 128);
        gemm_mma_kernel<HID, 2><<<grid, 256>>>(nullptr, N, HID2);
    }
    agg2_head_kernel<<<aggBlocks, warpsPerBlock * 32>>>(b2, W3, b3, out, N);
}